// round 1
// baseline (speedup 1.0000x reference)
#include <cuda_runtime.h>
#include <cstdint>

#define B_    4
#define N_    2048
#define DIM_  768
#define H_    12
#define DH_   64
#define M_TOT (B_ * N_)       // 8192
#define QKV_N (3 * DIM_)      // 2304
#define SCALE_ 0.125f         // 64^-0.5

// Scratch (device globals — allocation-free per harness rules)
__device__ float g_qkv[(size_t)M_TOT * QKV_N];   // [8192, 2304]
__device__ float g_attn[(size_t)M_TOT * DIM_];   // [8192, 768]  (B,N,H,Dh) flattened

// ---------------------------------------------------------------------------
// SGEMM: C[M,N] = A[M,K] @ B[K,N] (+ bias). Row-major. M%128==0, N%128==0, K%8==0.
// 128x128 block tile, BK=8, 256 threads, 8x8 per-thread microtile.
// ---------------------------------------------------------------------------
constexpr int BM = 128, BN = 128, BK = 8, TM = 8, TN = 8;

__global__ __launch_bounds__(256) void sgemm_kernel(
    const float* __restrict__ A, const float* __restrict__ Bm,
    float* __restrict__ C, int M, int N, int K,
    const float* __restrict__ bias)
{
    __shared__ float As[BK][BM];   // transposed A tile
    __shared__ float Bs[BK][BN];

    const int tid  = threadIdx.x;
    const int bm   = blockIdx.y * BM;
    const int bn   = blockIdx.x * BN;

    const int aRow = tid >> 1;            // 0..127
    const int aCol = (tid & 1) << 2;      // 0 or 4
    const int bRow = tid >> 5;            // 0..7
    const int bCol = (tid & 31) << 2;     // 0..124

    const int tr = (tid >> 4) * TM;       // 0..120
    const int tc = (tid & 15) * TN;       // 0..120

    float acc[TM][TN] = {};

    for (int k0 = 0; k0 < K; k0 += BK) {
        float4 a4 = *(const float4*)(A + (size_t)(bm + aRow) * K + k0 + aCol);
        As[aCol + 0][aRow] = a4.x;
        As[aCol + 1][aRow] = a4.y;
        As[aCol + 2][aRow] = a4.z;
        As[aCol + 3][aRow] = a4.w;
        *(float4*)&Bs[bRow][bCol] =
            *(const float4*)(Bm + (size_t)(k0 + bRow) * N + bn + bCol);
        __syncthreads();

        #pragma unroll
        for (int k = 0; k < BK; k++) {
            float ra[TM], rb[TN];
            #pragma unroll
            for (int i = 0; i < TM; i++) ra[i] = As[k][tr + i];
            #pragma unroll
            for (int j = 0; j < TN; j++) rb[j] = Bs[k][tc + j];
            #pragma unroll
            for (int i = 0; i < TM; i++)
                #pragma unroll
                for (int j = 0; j < TN; j++)
                    acc[i][j] = fmaf(ra[i], rb[j], acc[i][j]);
        }
        __syncthreads();
    }

    #pragma unroll
    for (int i = 0; i < TM; i++) {
        float* crow = C + (size_t)(bm + tr + i) * N + bn + tc;
        #pragma unroll
        for (int j = 0; j < TN; j += 4) {
            float4 v;
            v.x = acc[i][j + 0];
            v.y = acc[i][j + 1];
            v.z = acc[i][j + 2];
            v.w = acc[i][j + 3];
            if (bias) {
                v.x += bias[bn + tc + j + 0];
                v.y += bias[bn + tc + j + 1];
                v.z += bias[bn + tc + j + 2];
                v.w += bias[bn + tc + j + 3];
            }
            *(float4*)(crow + j) = v;
        }
    }
}

// ---------------------------------------------------------------------------
// Flash attention (fp32). One block = 64 query rows of one (b,h).
// Q,K in smem d-major [d][row] stride 68 (float4 aligned, 2-phase banks).
// V in smem [row][d] stride 68. P staged through smem for the PV GEMM.
// 256 threads: (ty,tx) in 16x16, each owns a 4x4 microtile.
// ---------------------------------------------------------------------------
#define FT    64
#define SSTR  68
#define FLASH_SMEM (4 * FT * SSTR * (int)sizeof(float))   // 69632 B

__global__ __launch_bounds__(256) void flash_kernel(
    const float* __restrict__ qkv, float* __restrict__ out)
{
    extern __shared__ float sm[];
    float* q_s = sm;                  // [64][68]  (d-major)
    float* k_s = q_s + FT * SSTR;     // [64][68]  (d-major)
    float* v_s = k_s + FT * SSTR;     // [64][68]  (row-major)
    float* p_s = v_s + FT * SSTR;     // [64][68]  (row-major)

    const int tid = threadIdx.x;
    const int bh  = blockIdx.y;
    const int b   = bh / H_;
    const int h   = bh % H_;
    const int q0  = blockIdx.x * FT;

    const size_t rowbase = (size_t)b * N_ * QKV_N;
    const int qoff = h * DH_;
    const int koff = DIM_ + h * DH_;
    const int voff = 2 * DIM_ + h * DH_;

    // Load Q tile once (transposed to d-major), pre-scaled
    #pragma unroll
    for (int i = 0; i < 16; i++) {
        int idx = tid + i * 256;
        int r = idx >> 6, d = idx & 63;
        q_s[d * SSTR + r] =
            qkv[rowbase + (size_t)(q0 + r) * QKV_N + qoff + d] * SCALE_;
    }

    const int ty = tid >> 4, tx = tid & 15;

    float m_i[4], l_i[4], acc[4][4];
    #pragma unroll
    for (int i = 0; i < 4; i++) {
        m_i[i] = -1e30f;
        l_i[i] = 0.0f;
        #pragma unroll
        for (int j = 0; j < 4; j++) acc[i][j] = 0.0f;
    }

    for (int t = 0; t < N_ / FT; t++) {
        __syncthreads();   // protect k_s/v_s/p_s from previous iteration readers
        const int kr0 = t * FT;
        #pragma unroll
        for (int i = 0; i < 16; i++) {
            int idx = tid + i * 256;
            int r = idx >> 6, d = idx & 63;
            size_t g = rowbase + (size_t)(kr0 + r) * QKV_N;
            k_s[d * SSTR + r] = qkv[g + koff + d];
            v_s[r * SSTR + d] = qkv[g + voff + d];
        }
        __syncthreads();

        // S = Q @ K^T  (4x4 per thread)
        float s[4][4] = {};
        #pragma unroll 4
        for (int d = 0; d < DH_; d++) {
            float4 qv = *(const float4*)&q_s[d * SSTR + ty * 4];
            float4 kv = *(const float4*)&k_s[d * SSTR + tx * 4];
            float qa[4] = {qv.x, qv.y, qv.z, qv.w};
            float ka[4] = {kv.x, kv.y, kv.z, kv.w};
            #pragma unroll
            for (int i = 0; i < 4; i++)
                #pragma unroll
                for (int j = 0; j < 4; j++)
                    s[i][j] = fmaf(qa[i], ka[j], s[i][j]);
        }

        // Online softmax: row reductions across the 16 tx lanes
        #pragma unroll
        for (int i = 0; i < 4; i++) {
            float mm = fmaxf(fmaxf(s[i][0], s[i][1]), fmaxf(s[i][2], s[i][3]));
            #pragma unroll
            for (int o = 1; o < 16; o <<= 1)
                mm = fmaxf(mm, __shfl_xor_sync(0xffffffffu, mm, o));
            float mnew = fmaxf(m_i[i], mm);
            float alpha = __expf(m_i[i] - mnew);
            m_i[i] = mnew;

            float rs = 0.0f;
            #pragma unroll
            for (int j = 0; j < 4; j++) {
                s[i][j] = __expf(s[i][j] - mnew);
                rs += s[i][j];
            }
            #pragma unroll
            for (int o = 1; o < 16; o <<= 1)
                rs += __shfl_xor_sync(0xffffffffu, rs, o);
            l_i[i] = l_i[i] * alpha + rs;

            #pragma unroll
            for (int j = 0; j < 4; j++) acc[i][j] *= alpha;

            // stage P row-chunk to smem
            float4 pv;
            pv.x = s[i][0]; pv.y = s[i][1]; pv.z = s[i][2]; pv.w = s[i][3];
            *(float4*)&p_s[(ty * 4 + i) * SSTR + tx * 4] = pv;
        }
        __syncthreads();

        // acc += P @ V
        #pragma unroll 4
        for (int j = 0; j < FT; j++) {
            float pa[4];
            #pragma unroll
            for (int i = 0; i < 4; i++) pa[i] = p_s[(ty * 4 + i) * SSTR + j];
            float4 vv = *(const float4*)&v_s[j * SSTR + tx * 4];
            float va[4] = {vv.x, vv.y, vv.z, vv.w};
            #pragma unroll
            for (int i = 0; i < 4; i++)
                #pragma unroll
                for (int jj = 0; jj < 4; jj++)
                    acc[i][jj] = fmaf(pa[i], va[jj], acc[i][jj]);
        }
    }

    // Normalize and write to [B*N, H*Dh]
    #pragma unroll
    for (int i = 0; i < 4; i++) {
        float inv = 1.0f / l_i[i];
        float4 o;
        o.x = acc[i][0] * inv;
        o.y = acc[i][1] * inv;
        o.z = acc[i][2] * inv;
        o.w = acc[i][3] * inv;
        size_t row = (size_t)(b * N_ + q0 + ty * 4 + i);
        *(float4*)&out[row * DIM_ + h * DH_ + tx * 4] = o;
    }
}

// ---------------------------------------------------------------------------
// Launch
// ---------------------------------------------------------------------------
extern "C" void kernel_launch(void* const* d_in, const int* in_sizes, int n_in,
                              void* d_out, int out_size)
{
    const float* x      = (const float*)d_in[0];   // [4,2048,768]
    const float* w_qkv  = (const float*)d_in[1];   // [768,2304]
    const float* w_proj = (const float*)d_in[2];   // [768,768]
    const float* b_proj = (const float*)d_in[3];   // [768]
    float* out = (float*)d_out;                    // [4,2048,768]

    float* qkv = nullptr;
    float* attn = nullptr;
    cudaGetSymbolAddress((void**)&qkv, g_qkv);
    cudaGetSymbolAddress((void**)&attn, g_attn);

    cudaFuncSetAttribute(flash_kernel,
                         cudaFuncAttributeMaxDynamicSharedMemorySize,
                         FLASH_SMEM);

    // 1) QKV = X @ Wqkv          [8192,2304]
    dim3 g1(QKV_N / BN, M_TOT / BM);
    sgemm_kernel<<<g1, 256>>>(x, w_qkv, qkv, M_TOT, QKV_N, DIM_, nullptr);

    // 2) Flash attention per (b,h), 64-row query tiles
    dim3 g2(N_ / FT, B_ * H_);
    flash_kernel<<<g2, 256, FLASH_SMEM>>>(qkv, attn);

    // 3) OUT = ATTN @ Wproj + b  [8192,768]
    dim3 g3(DIM_ / BN, M_TOT / BM);
    sgemm_kernel<<<g3, 256>>>(attn, w_proj, out, M_TOT, DIM_, DIM_, b_proj);
}